// round 13
// baseline (speedup 1.0000x reference)
#include <cuda_runtime.h>
#include <cuda_fp16.h>
#include <math.h>
#include <stdint.h>

#define N_RAYS   4096
#define PSTEPS   254
#define P_INNER  231
#define MTOT     (N_RAYS*PSTEPS)      // 1,040,384
#define NT256    (MTOT/256)           // 4064
#define WORLD    160
#define S2       (WORLD*WORLD)
#define S3       (WORLD*WORLD*WORLD)
#define ACT_SHIFT (-9.210240371976183f)
#define BG_LEN   0.2f
#define GRID_MLP 444                  // 3 CTAs per SM

// ---------------- scratch ----------------
__device__ uint4    g_pack[S3*2];       // per-voxel record: 12 fp16 k0 + fp32 density + pad (32 B)
__device__ uint16_t g_f16[MTOT*16];     // k0 features fp16 rows (12 real + 4 pad)
__device__ float    g_vembf[N_RAYS*27]; // view embedding fp32
__device__ uint16_t g_h0v[N_RAYS*128];  // per-ray layer0 contribution of vemb + b0 (fp16)
__device__ float    g_w[MTOT];

// ---------------- helpers ----------------
__device__ __forceinline__ uint16_t f2h(float f) {
    return __half_as_ushort(__float2half_rn(f));
}
__device__ __forceinline__ uint32_t pack_h2(float f0, float f1) {   // f0 -> low half
    __half2 v = __floats2half2_rn(f0, f1);
    return *reinterpret_cast<uint32_t*>(&v);
}
__device__ __forceinline__ uint32_t smem_u32(const void* p) {
    uint32_t a;
    asm("{ .reg .u64 t; cvta.to.shared.u64 t, %1; cvt.u32.u64 %0, t; }" : "=r"(a) : "l"(p));
    return a;
}

#define LDSM_X4(r0,r1,r2,r3,addr) \
    asm volatile("ldmatrix.sync.aligned.m8n8.x4.shared.b16 {%0,%1,%2,%3}, [%4];" \
        : "=r"(r0), "=r"(r1), "=r"(r2), "=r"(r3) : "r"(addr))

#define LDSM_X2(r0,r1,addr) \
    asm volatile("ldmatrix.sync.aligned.m8n8.x2.shared.b16 {%0,%1}, [%2];" \
        : "=r"(r0), "=r"(r1) : "r"(addr))

// f32-accumulator MMA (layer 2 only)
#define MMA_F16(c, a0,a1,a2,a3, b0,b1) \
    asm volatile("mma.sync.aligned.m16n8k16.row.col.f32.f16.f16.f32 " \
        "{%0,%1,%2,%3}, {%4,%5,%6,%7}, {%8,%9}, {%0,%1,%2,%3};" \
        : "+f"((c)[0]), "+f"((c)[1]), "+f"((c)[2]), "+f"((c)[3]) \
        : "r"(a0), "r"(a1), "r"(a2), "r"(a3), "r"(b0), "r"(b1))

// f16-accumulator MMA (layers 0/1): D,C = 2x .f16x2 registers
#define MMA_F16H(c, a0,a1,a2,a3, b0,b1) \
    asm volatile("mma.sync.aligned.m16n8k16.row.col.f16.f16.f16.f16 " \
        "{%0,%1}, {%2,%3,%4,%5}, {%6,%7}, {%0,%1};" \
        : "+r"((c)[0]), "+r"((c)[1]) \
        : "r"(a0), "r"(a1), "r"(a2), "r"(a3), "r"(b0), "r"(b1))

#define CP_ASYNC16(dst, src) \
    asm volatile("cp.async.cg.shared.global [%0], [%1], 16;" :: "r"(dst), "l"(src) : "memory")
#define CP_ASYNC4(dst, src) \
    asm volatile("cp.async.ca.shared.global [%0], [%1], 4;" :: "r"(dst), "l"(src) : "memory")
#define CP_COMMIT() asm volatile("cp.async.commit_group;" ::: "memory")
#define CP_WAIT0()  asm volatile("cp.async.wait_group 0;" ::: "memory")

// ---------------- K0: grid repack (channel-interleaved 32B records) ----------------
__global__ void k_pack(const float* __restrict__ dgrid, const float* __restrict__ k0g)
{
    int idx = blockIdx.x * blockDim.x + threadIdx.x;
    if (idx >= S3) return;
    uint32_t h[6];
    #pragma unroll
    for (int c = 0; c < 6; c++)
        h[c] = pack_h2(__ldg(&k0g[(2*c)*S3 + idx]), __ldg(&k0g[(2*c+1)*S3 + idx]));
    float d = __ldg(&dgrid[idx]);
    g_pack[(size_t)idx*2+0] = make_uint4(h[0], h[1], h[2], h[3]);
    g_pack[(size_t)idx*2+1] = make_uint4(h[4], h[5], __float_as_uint(d), 0u);
}

// ---------------- K1: warp-per-ray sampling + interp + vemb + transmittance scan ----------------
__global__ void k_sample(const float* __restrict__ ro, const float* __restrict__ rdir,
                         const float* __restrict__ vdirs, const int* __restrict__ stepsize,
                         float* __restrict__ out)
{
    int gw = (blockIdx.x * blockDim.x + threadIdx.x) >> 5;   // ray id
    int lane = threadIdx.x & 31;
    if (gw >= N_RAYS) return;

    float v0 = __ldg(&vdirs[gw*3+0]);
    float v1 = __ldg(&vdirs[gw*3+1]);
    float v2 = __ldg(&vdirs[gw*3+2]);
    if (lane < 27) {
        float v;
        if (lane < 3) {
            v = (lane == 0) ? v0 : (lane == 1) ? v1 : v2;
        } else {
            int kk = (lane < 15) ? (lane - 3) : (lane - 15);
            int c = kk >> 2, e = kk & 3;
            float dc = (c == 0) ? v0 : (c == 1) ? v1 : v2;
            float vv = dc * (float)(1 << e);
            v = (lane < 15) ? sinf(vv) : cosf(vv);
        }
        g_vembf[gw*27 + lane] = v;
    }

    float dx = __ldg(&rdir[gw*3+0]), dy = __ldg(&rdir[gw*3+1]), dz = __ldg(&rdir[gw*3+2]);
    float inv = rsqrtf(dx*dx + dy*dy + dz*dz);
    dx *= inv; dy *= inv; dz *= inv;
    float ox = __ldg(&ro[gw*3+0]), oy = __ldg(&ro[gw*3+1]), oz = __ldg(&ro[gw*3+2]);

    int sv = *stepsize;
    float interval = (sv > 0 && sv < 1000000) ? (float)sv : __int_as_float(sv);

    float T = 1.0f;
    int base = gw * PSTEPS;
    const float SQ3x2 = 3.4641016151377546f;

    #pragma unroll 1
    for (int chunk = 0; chunk < 8; chunk++) {
        int p = chunk*32 + lane;
        bool valid = p < PSTEPS;
        int pe = valid ? p : (PSTEPS - 1);

        float t;
        if (pe < P_INNER) {
            t = SQ3x2 * ((float)pe + 0.5f) * (1.0f / 231.0f);
        } else {
            int q = pe - P_INNER;
            float L0 = 1.0f - (float)q     * (0.999f / 23.0f);
            float L1 = 1.0f - (float)(q+1) * (0.999f / 23.0f);
            t = 0.5f * SQ3x2 * (1.0f / L0 + 1.0f / L1);
        }

        float px = ox + dx * t, py = oy + dy * t, pz = oz + dz * t;
        float nm = fmaxf(fabsf(px), fmaxf(fabsf(py), fabsf(pz)));
        if (nm > 1.0f) {
            float sc = (1.0f + BG_LEN - BG_LEN / nm) / nm;
            px *= sc; py *= sc; pz *= sc;
        }

        const float GS = 159.0f / 2.4f;
        float gx = fminf(fmaxf((px + 1.2f) * GS, 0.0f), 159.0f);
        float gy = fminf(fmaxf((py + 1.2f) * GS, 0.0f), 159.0f);
        float gz = fminf(fmaxf((pz + 1.2f) * GS, 0.0f), 159.0f);
        int ix = min((int)gx, 158);
        int iy = min((int)gy, 158);
        int iz = min((int)gz, 158);
        float fx = gx - (float)ix, fy = gy - (float)iy, fz = gz - (float)iz;

        int vb = (ix * WORLD + iy) * WORLD + iz;
        float w00 = (1.f-fx)*(1.f-fy), w01 = (1.f-fx)*fy, w10 = fx*(1.f-fy), w11 = fx*fy;
        float wz0 = 1.f - fz, wz1 = fz;

        float wt[8];
        wt[0]=w00*wz0; wt[1]=w00*wz1; wt[2]=w01*wz0; wt[3]=w01*wz1;
        wt[4]=w10*wz0; wt[5]=w10*wz1; wt[6]=w11*wz0; wt[7]=w11*wz1;
        int off[8];
        off[0]=vb;          off[1]=vb+1;
        off[2]=vb+WORLD;    off[3]=vb+WORLD+1;
        off[4]=vb+S2;       off[5]=vb+S2+1;
        off[6]=vb+S2+WORLD; off[7]=vb+S2+WORLD+1;

        float acc[12];
        #pragma unroll
        for (int c = 0; c < 12; c++) acc[c] = 0.0f;
        float dsum = 0.0f;

        #pragma unroll
        for (int u = 0; u < 8; u++) {
            const uint4* rec = &g_pack[(size_t)off[u]*2];
            uint4 qa = __ldg(&rec[0]);
            uint4 qb = __ldg(&rec[1]);
            float wtu = wt[u];
            float2 f;
            f = __half22float2(*(const __half2*)&qa.x); acc[0] += wtu*f.x; acc[1] += wtu*f.y;
            f = __half22float2(*(const __half2*)&qa.y); acc[2] += wtu*f.x; acc[3] += wtu*f.y;
            f = __half22float2(*(const __half2*)&qa.z); acc[4] += wtu*f.x; acc[5] += wtu*f.y;
            f = __half22float2(*(const __half2*)&qa.w); acc[6] += wtu*f.x; acc[7] += wtu*f.y;
            f = __half22float2(*(const __half2*)&qb.x); acc[8] += wtu*f.x; acc[9] += wtu*f.y;
            f = __half22float2(*(const __half2*)&qb.y); acc[10]+= wtu*f.x; acc[11]+= wtu*f.y;
            dsum += wtu * __uint_as_float(qb.z);
        }

        float x = dsum + ACT_SHIFT;
        float sp = (x > 20.0f) ? x : log1pf(expf(x));
        float alpha = valid ? (1.0f - expf(-interval * sp)) : 0.0f;

        if (valid) {
            uint32_t ph[8];
            #pragma unroll
            for (int c = 0; c < 6; c++) ph[c] = pack_h2(acc[2*c], acc[2*c+1]);
            ph[6] = ph[7] = 0u;
            uint4* dh = (uint4*)&g_f16[(size_t)(base + p)*16];
            dh[0] = make_uint4(ph[0],ph[1],ph[2],ph[3]);
            dh[1] = make_uint4(ph[4],ph[5],ph[6],ph[7]);
        }

        float q = 1.0f - alpha;
        float incl = q;
        #pragma unroll
        for (int dlt = 1; dlt < 32; dlt <<= 1) {
            float o = __shfl_up_sync(0xffffffffu, incl, dlt);
            if (lane >= dlt) incl *= o;
        }
        float excl = __shfl_up_sync(0xffffffffu, incl, 1);
        if (lane == 0) excl = 1.0f;
        if (valid) g_w[base + p] = alpha * T * excl;
        float tot = __shfl_sync(0xffffffffu, incl, 31);
        T *= tot;
    }
    if (lane == 0) {
        out[gw*3+0] = T; out[gw*3+1] = T; out[gw*3+2] = T;   // BG = 1.0
    }
}

// ---------------- K2b: per-ray layer0 view contribution (fp16): h0v = b0 + vemb @ W0[12:39] ----------------
__global__ void k_h0v(const float* __restrict__ w0, const float* __restrict__ b0)
{
    int gid = blockIdx.x * blockDim.x + threadIdx.x;
    int r = gid >> 7, n = gid & 127;
    float acc = __ldg(&b0[n]);
    #pragma unroll
    for (int k = 0; k < 27; k++)
        acc = fmaf(g_vembf[r*27 + k], __ldg(&w0[(12+k)*128 + n]), acc);
    g_h0v[r*128 + n] = f2h(acc);
}

// ---------------- K3: persistent fp16-acc MLP, 256 thr (8 warps, 256-row supertile), 3 CTAs/SM ----------------
// smem layout (bytes)
#define SM_B1V   0        // 512:   b1 as half2[64] (256 B used)
#define SM_H0    512      // 1536:  [2 buf][3 rays][128 half]
#define SM_A0    2048     // 24576: [2 buf][256 rows][48 B]
#define SM_B0    26624    // 6144:  [128 n][48 B] (k 0..15 real)
#define SM_B1    32768    // 34816: [128 n][272 B] (k 0..127 real)
#define SM_B2    67584    // 2176:  [8 n][272 B] (n 0..2 real)
#define SMEM_TOTAL 69760

__global__ void __launch_bounds__(256, 3) k_mlp(
    const float* __restrict__ w0, const float* __restrict__ b0,
    const float* __restrict__ w1, const float* __restrict__ b1,
    const float* __restrict__ w2, const float* __restrict__ b2,
    float* __restrict__ out)
{
    extern __shared__ unsigned char smem[];
    uint32_t sb = smem_u32(smem);
    int tid = threadIdx.x;
    int w = tid >> 5, l = tid & 31;
    int g = l >> 2, tg = l & 3;

    // ---- one-time weight staging (fp16, [n][k] layout) ----
    if (tid < 64) ((uint32_t*)(smem + SM_B1V))[tid] = pack_h2(b1[2*tid], b1[2*tid+1]);

    for (int idx = tid; idx < 128*16; idx += 256) {
        int n = idx & 127, k = idx >> 7;
        float v = (k < 12) ? w0[k*128 + n] : 0.0f;
        *(uint16_t*)(smem + SM_B0 + n*48 + k*2) = f2h(v);
    }
    for (int idx = tid; idx < 128*128; idx += 256) {
        int n = idx & 127, k = idx >> 7;
        *(uint16_t*)(smem + SM_B1 + n*272 + k*2) = f2h(w1[k*128 + n]);
    }
    for (int idx = tid; idx < 8*128; idx += 256) {
        int n = idx & 7, k = idx >> 3;
        float v = (n < 3) ? w2[k*3 + n] : 0.0f;
        *(uint16_t*)(smem + SM_B2 + n*272 + k*2) = f2h(v);
    }
    float b2r0 = __ldg(&b2[0]), b2r1 = __ldg(&b2[1]), b2r2 = __ldg(&b2[2]);
    const __half2* b1h2 = (const __half2*)(smem + SM_B1V);
    const __half2 hz = __floats2half2_rn(0.f, 0.f);

    // ---- lane-invariant ldmatrix addresses ----
    uint32_t rowA = 32u*w + (l & 7) + ((l >> 3) & 1) * 8;   // rows 32w..; block 1 = +16 rows (768B)
    uint32_t colA = (uint32_t)(l >> 4) * 16;
    uint32_t lrow = (l & 7) + ((l >> 4) & 1) * 8;
    uint32_t lcol = ((l >> 3) & 1) * 16;
    uint32_t aB0 = sb + SM_B0 + lrow*48  + lcol;
    uint32_t aB1 = sb + SM_B1 + lrow*272 + lcol;
    uint32_t aB2 = sb + SM_B2 + (uint32_t)(l & 7)*272 + ((l >> 3) & 1)*16;

    int srow = tid;   // each thread stages one full row (32 B), 256 rows
    uint32_t a0dst0 = sb + SM_A0 + srow*48;

    // ---- prime A0 + H0 buffer 0 (cp.async) ----
    int m = blockIdx.x;
    if (m < NT256) {
        const char* src = (const char*)&g_f16[(size_t)(m*256+srow)*16];
        CP_ASYNC16(a0dst0,      src);
        CP_ASYNC16(a0dst0 + 16, src + 16);
        // H0: 3 consecutive rays starting at rA; 192 words of 4B staged by threads 0..191
        int rA = (m*256) / PSTEPS;
        if (tid < 192) {
            int ray = min(rA + tid/64, N_RAYS-1);
            int li  = tid % 64;
            CP_ASYNC4(sb + SM_H0 + (uint32_t)(tid/64)*256u + li*4,
                      (const char*)&g_h0v[(size_t)ray*128 + li*2]);
        }
        CP_COMMIT();
        CP_WAIT0();
    }
    __syncthreads();

    // ---- preload layer-2 B fragments (tile-invariant) ----
    uint32_t b2f[8][2];
    #pragma unroll
    for (int p = 0; p < 8; p++) LDSM_X2(b2f[p][0], b2f[p][1], aB2 + p*32);

    int buf = 0;

    for (; m < NT256; m += gridDim.x) {
        int mbase = m * 256;
        int mn = m + gridDim.x;
        bool hn = mn < NT256;
        if (hn) {   // async-stage next supertile into alternate buffer
            uint32_t ab = a0dst0 + (uint32_t)(buf^1)*12288u;
            const char* src = (const char*)&g_f16[(size_t)(mn*256+srow)*16];
            CP_ASYNC16(ab,      src);
            CP_ASYNC16(ab + 16, src + 16);
            int rAn = (mn*256) / PSTEPS;
            if (tid < 192) {
                int ray = min(rAn + tid/64, N_RAYS-1);
                int li  = tid % 64;
                CP_ASYNC4(sb + SM_H0 + (uint32_t)(buf^1)*768u + (uint32_t)(tid/64)*256u + li*4,
                          (const char*)&g_h0v[(size_t)ray*128 + li*2]);
            }
            CP_COMMIT();
        }

        // sample ids: [block][rowhalf]
        int s00 = mbase + 32*w + g;
        int s01 = s00 + 8;
        int s10 = s00 + 16;
        int s11 = s00 + 24;
        int r00 = s00 / PSTEPS, r01 = s01 / PSTEPS;
        int r10 = s10 / PSTEPS, r11 = s11 / PSTEPS;
        int rAc = mbase / PSTEPS;
        const __half* h0sb = (const __half*)(smem + SM_H0 + (uint32_t)buf*768u);
        const __half* hp[2][2] = {
            { h0sb + (r00 - rAc)*128, h0sb + (r01 - rAc)*128 },
            { h0sb + (r10 - rAc)*128, h0sb + (r11 - rAc)*128 } };

        // ---- layer 0: K=16, f16-acc MMA -> A1 frags in registers ----
        uint32_t aA = sb + SM_A0 + (uint32_t)buf*12288u + rowA*48 + colA;
        uint32_t a0f[2][4];
        LDSM_X4(a0f[0][0],a0f[0][1],a0f[0][2],a0f[0][3], aA);
        LDSM_X4(a0f[1][0],a0f[1][1],a0f[1][2],a0f[1][3], aA + 768);

        uint32_t aF[2][8][4];
        #pragma unroll
        for (int p = 0; p < 8; p++) {
            uint32_t cc[2][2][2];
            #pragma unroll
            for (int b = 0; b < 2; b++)
                #pragma unroll
                for (int hh = 0; hh < 2; hh++) { cc[b][hh][0] = 0u; cc[b][hh][1] = 0u; }
            uint32_t bb0,bb1,bb2,bb3;
            LDSM_X4(bb0,bb1,bb2,bb3, aB0 + p*768);
            #pragma unroll
            for (int b = 0; b < 2; b++) {
                MMA_F16H(cc[b][0], a0f[b][0],a0f[b][1],a0f[b][2],a0f[b][3], bb0,bb1);
                MMA_F16H(cc[b][1], a0f[b][0],a0f[b][1],a0f[b][2],a0f[b][3], bb2,bb3);
            }
            #pragma unroll
            for (int b = 0; b < 2; b++)
                #pragma unroll
                for (int hh = 0; hh < 2; hh++) {
                    int col = p*16 + hh*8 + tg*2;
                    __half2 hA = *(const __half2*)&hp[b][0][col];
                    __half2 hB = *(const __half2*)&hp[b][1][col];
                    __half2 o0 = __hmax2(__hadd2(*(__half2*)&cc[b][hh][0], hA), hz);
                    __half2 o1 = __hmax2(__hadd2(*(__half2*)&cc[b][hh][1], hB), hz);
                    aF[b][p][0+hh*2] = *(uint32_t*)&o0;
                    aF[b][p][1+hh*2] = *(uint32_t*)&o1;
                }
        }

        // ---- layer 1 (K=128, f16-acc) + fused layer 2 MMA (f32-acc) per 16-col chunk ----
        float c2[2][4];
        c2[0][0]=c2[0][1]=c2[0][2]=c2[0][3]=0.f;
        c2[1][0]=c2[1][1]=c2[1][2]=c2[1][3]=0.f;

        #pragma unroll
        for (int p = 0; p < 8; p++) {
            uint32_t cc[2][2][2];
            #pragma unroll
            for (int b = 0; b < 2; b++)
                #pragma unroll
                for (int hh = 0; hh < 2; hh++) { cc[b][hh][0] = 0u; cc[b][hh][1] = 0u; }
            #pragma unroll
            for (int ks = 0; ks < 8; ks++) {
                uint32_t bb0,bb1,bb2,bb3;
                LDSM_X4(bb0,bb1,bb2,bb3, aB1 + p*4352 + ks*32);
                #pragma unroll
                for (int b = 0; b < 2; b++) {
                    MMA_F16H(cc[b][0], aF[b][ks][0],aF[b][ks][1],aF[b][ks][2],aF[b][ks][3], bb0,bb1);
                    MMA_F16H(cc[b][1], aF[b][ks][0],aF[b][ks][1],aF[b][ks][2],aF[b][ks][3], bb2,bb3);
                }
            }
            #pragma unroll
            for (int b = 0; b < 2; b++) {
                uint32_t hf[4];
                #pragma unroll
                for (int hh = 0; hh < 2; hh++) {
                    int col = p*16 + hh*8 + tg*2;
                    __half2 bh = b1h2[col >> 1];
                    __half2 o0 = __hmax2(__hadd2(*(__half2*)&cc[b][hh][0], bh), hz);
                    __half2 o1 = __hmax2(__hadd2(*(__half2*)&cc[b][hh][1], bh), hz);
                    hf[0+hh*2] = *(uint32_t*)&o0;
                    hf[1+hh*2] = *(uint32_t*)&o1;
                }
                MMA_F16(c2[b], hf[0],hf[1],hf[2],hf[3], b2f[p][0], b2f[p][1]);
            }
        }

        // ---- epilogue: sigmoid + weighted atomic, direct from c2 fragments ----
        if (tg == 0) {
            #pragma unroll
            for (int b = 0; b < 2; b++) {
                int sA = (b == 0) ? s00 : s10;
                int sB = (b == 0) ? s01 : s11;
                int rA_ = (b == 0) ? r00 : r10;
                int rB_ = (b == 0) ? r01 : r11;
                float wgA = g_w[sA], wgB = g_w[sB];
                atomicAdd(&out[rA_*3+0], wgA / (1.0f + __expf(-(c2[b][0] + b2r0))));
                atomicAdd(&out[rA_*3+1], wgA / (1.0f + __expf(-(c2[b][1] + b2r1))));
                atomicAdd(&out[rB_*3+0], wgB / (1.0f + __expf(-(c2[b][2] + b2r0))));
                atomicAdd(&out[rB_*3+1], wgB / (1.0f + __expf(-(c2[b][3] + b2r1))));
            }
        } else if (tg == 1) {
            #pragma unroll
            for (int b = 0; b < 2; b++) {
                int sA = (b == 0) ? s00 : s10;
                int sB = (b == 0) ? s01 : s11;
                int rA_ = (b == 0) ? r00 : r10;
                int rB_ = (b == 0) ? r01 : r11;
                float wgA = g_w[sA], wgB = g_w[sB];
                atomicAdd(&out[rA_*3+2], wgA / (1.0f + __expf(-(c2[b][0] + b2r2))));
                atomicAdd(&out[rB_*3+2], wgB / (1.0f + __expf(-(c2[b][2] + b2r2))));
            }
        }

        if (hn) CP_WAIT0();
        __syncthreads();
        buf ^= 1;
    }
}

// ---------------- launcher ----------------
extern "C" void kernel_launch(void* const* d_in, const int* in_sizes, int n_in,
                              void* d_out, int out_size)
{
    const float* rays_o   = (const float*)d_in[0];
    const float* rays_d   = (const float*)d_in[1];
    const float* viewdirs = (const float*)d_in[2];
    const float* dgrid    = (const float*)d_in[3];
    const float* k0g      = (const float*)d_in[4];
    const float* w0 = (const float*)d_in[5];
    const float* b0 = (const float*)d_in[6];
    const float* w1 = (const float*)d_in[7];
    const float* b1 = (const float*)d_in[8];
    const float* w2 = (const float*)d_in[9];
    const float* b2 = (const float*)d_in[10];
    const int* stepsize = (const int*)d_in[11];
    float* out = (float*)d_out;

    cudaFuncSetAttribute(k_mlp, cudaFuncAttributeMaxDynamicSharedMemorySize, SMEM_TOTAL);

    k_pack<<<(S3 + 255) / 256, 256>>>(dgrid, k0g);
    k_sample<<<(N_RAYS * 32 + 255) / 256, 256>>>(rays_o, rays_d, viewdirs, stepsize, out);
    k_h0v<<<(N_RAYS * 128) / 256, 256>>>(w0, b0);
    k_mlp<<<GRID_MLP, 256, SMEM_TOTAL>>>(w0, b0, w1, b1, w2, b2, out);
}

// round 14
// speedup vs baseline: 1.3085x; 1.3085x over previous
#include <cuda_runtime.h>
#include <cuda_fp16.h>
#include <math.h>
#include <stdint.h>

#define N_RAYS   4096
#define PSTEPS   254
#define P_INNER  231
#define MTOT     (N_RAYS*PSTEPS)      // 1,040,384
#define NTILES   (MTOT/128)           // 8128
#define WORLD    160
#define S2       (WORLD*WORLD)
#define S3       (WORLD*WORLD*WORLD)
#define ACT_SHIFT (-9.210240371976183f)
#define BG_LEN   0.2f
#define GRID_MLP 444                  // 3 CTAs per SM

// ---------------- scratch ----------------
__device__ uint4    g_pack[S3*2];       // per-voxel record: 12 fp16 k0 + fp32 density + pad (32 B)
__device__ uint16_t g_f16[MTOT*16];     // k0 features fp16 rows (12 real + 4 pad)
__device__ float    g_vembf[N_RAYS*27]; // view embedding fp32
__device__ uint16_t g_h0v[N_RAYS*128];  // per-ray layer0 contribution of vemb + b0 (fp16)
__device__ float    g_w[MTOT];

// ---------------- helpers ----------------
__device__ __forceinline__ uint16_t f2h(float f) {
    return __half_as_ushort(__float2half_rn(f));
}
__device__ __forceinline__ uint32_t pack_h2(float f0, float f1) {   // f0 -> low half
    __half2 v = __floats2half2_rn(f0, f1);
    return *reinterpret_cast<uint32_t*>(&v);
}
__device__ __forceinline__ uint32_t smem_u32(const void* p) {
    uint32_t a;
    asm("{ .reg .u64 t; cvta.to.shared.u64 t, %1; cvt.u32.u64 %0, t; }" : "=r"(a) : "l"(p));
    return a;
}

#define LDSM_X4(r0,r1,r2,r3,addr) \
    asm volatile("ldmatrix.sync.aligned.m8n8.x4.shared.b16 {%0,%1,%2,%3}, [%4];" \
        : "=r"(r0), "=r"(r1), "=r"(r2), "=r"(r3) : "r"(addr))

#define LDSM_X2(r0,r1,addr) \
    asm volatile("ldmatrix.sync.aligned.m8n8.x2.shared.b16 {%0,%1}, [%2];" \
        : "=r"(r0), "=r"(r1) : "r"(addr))

// f32-accumulator MMA (layer 2 only)
#define MMA_F16(c, a0,a1,a2,a3, b0,b1) \
    asm volatile("mma.sync.aligned.m16n8k16.row.col.f32.f16.f16.f32 " \
        "{%0,%1,%2,%3}, {%4,%5,%6,%7}, {%8,%9}, {%0,%1,%2,%3};" \
        : "+f"((c)[0]), "+f"((c)[1]), "+f"((c)[2]), "+f"((c)[3]) \
        : "r"(a0), "r"(a1), "r"(a2), "r"(a3), "r"(b0), "r"(b1))

// f16-accumulator MMA (layers 0/1): D,C = 2x .f16x2 registers
#define MMA_F16H(c, a0,a1,a2,a3, b0,b1) \
    asm volatile("mma.sync.aligned.m16n8k16.row.col.f16.f16.f16.f16 " \
        "{%0,%1}, {%2,%3,%4,%5}, {%6,%7}, {%0,%1};" \
        : "+r"((c)[0]), "+r"((c)[1]) \
        : "r"(a0), "r"(a1), "r"(a2), "r"(a3), "r"(b0), "r"(b1))

#define CP_ASYNC16(dst, src) \
    asm volatile("cp.async.cg.shared.global [%0], [%1], 16;" :: "r"(dst), "l"(src) : "memory")
#define CP_ASYNC4(dst, src) \
    asm volatile("cp.async.ca.shared.global [%0], [%1], 4;" :: "r"(dst), "l"(src) : "memory")
#define CP_COMMIT() asm volatile("cp.async.commit_group;" ::: "memory")
#define CP_WAIT0()  asm volatile("cp.async.wait_group 0;" ::: "memory")

// ---------------- K0: grid repack (channel-interleaved 32B records) ----------------
__global__ void k_pack(const float* __restrict__ dgrid, const float* __restrict__ k0g)
{
    int idx = blockIdx.x * blockDim.x + threadIdx.x;
    if (idx >= S3) return;
    uint32_t h[6];
    #pragma unroll
    for (int c = 0; c < 6; c++)
        h[c] = pack_h2(__ldg(&k0g[(2*c)*S3 + idx]), __ldg(&k0g[(2*c+1)*S3 + idx]));
    float d = __ldg(&dgrid[idx]);
    g_pack[(size_t)idx*2+0] = make_uint4(h[0], h[1], h[2], h[3]);
    g_pack[(size_t)idx*2+1] = make_uint4(h[4], h[5], __float_as_uint(d), 0u);
}

// ---------------- K1: warp-per-ray sampling + interp + vemb + transmittance scan ----------------
__global__ void k_sample(const float* __restrict__ ro, const float* __restrict__ rdir,
                         const float* __restrict__ vdirs, const int* __restrict__ stepsize,
                         float* __restrict__ out)
{
    int gw = (blockIdx.x * blockDim.x + threadIdx.x) >> 5;   // ray id
    int lane = threadIdx.x & 31;
    if (gw >= N_RAYS) return;

    float v0 = __ldg(&vdirs[gw*3+0]);
    float v1 = __ldg(&vdirs[gw*3+1]);
    float v2 = __ldg(&vdirs[gw*3+2]);
    if (lane < 27) {
        float v;
        if (lane < 3) {
            v = (lane == 0) ? v0 : (lane == 1) ? v1 : v2;
        } else {
            int kk = (lane < 15) ? (lane - 3) : (lane - 15);
            int c = kk >> 2, e = kk & 3;
            float dc = (c == 0) ? v0 : (c == 1) ? v1 : v2;
            float vv = dc * (float)(1 << e);
            v = (lane < 15) ? sinf(vv) : cosf(vv);
        }
        g_vembf[gw*27 + lane] = v;
    }

    float dx = __ldg(&rdir[gw*3+0]), dy = __ldg(&rdir[gw*3+1]), dz = __ldg(&rdir[gw*3+2]);
    float inv = rsqrtf(dx*dx + dy*dy + dz*dz);
    dx *= inv; dy *= inv; dz *= inv;
    float ox = __ldg(&ro[gw*3+0]), oy = __ldg(&ro[gw*3+1]), oz = __ldg(&ro[gw*3+2]);

    int sv = *stepsize;
    float interval = (sv > 0 && sv < 1000000) ? (float)sv : __int_as_float(sv);

    float T = 1.0f;
    int base = gw * PSTEPS;
    const float SQ3x2 = 3.4641016151377546f;

    #pragma unroll 1
    for (int chunk = 0; chunk < 8; chunk++) {
        int p = chunk*32 + lane;
        bool valid = p < PSTEPS;
        int pe = valid ? p : (PSTEPS - 1);

        float t;
        if (pe < P_INNER) {
            t = SQ3x2 * ((float)pe + 0.5f) * (1.0f / 231.0f);
        } else {
            int q = pe - P_INNER;
            float L0 = 1.0f - (float)q     * (0.999f / 23.0f);
            float L1 = 1.0f - (float)(q+1) * (0.999f / 23.0f);
            t = 0.5f * SQ3x2 * (1.0f / L0 + 1.0f / L1);
        }

        float px = ox + dx * t, py = oy + dy * t, pz = oz + dz * t;
        float nm = fmaxf(fabsf(px), fmaxf(fabsf(py), fabsf(pz)));
        if (nm > 1.0f) {
            float sc = (1.0f + BG_LEN - BG_LEN / nm) / nm;
            px *= sc; py *= sc; pz *= sc;
        }

        const float GS = 159.0f / 2.4f;
        float gx = fminf(fmaxf((px + 1.2f) * GS, 0.0f), 159.0f);
        float gy = fminf(fmaxf((py + 1.2f) * GS, 0.0f), 159.0f);
        float gz = fminf(fmaxf((pz + 1.2f) * GS, 0.0f), 159.0f);
        int ix = min((int)gx, 158);
        int iy = min((int)gy, 158);
        int iz = min((int)gz, 158);
        float fx = gx - (float)ix, fy = gy - (float)iy, fz = gz - (float)iz;

        int vb = (ix * WORLD + iy) * WORLD + iz;
        float w00 = (1.f-fx)*(1.f-fy), w01 = (1.f-fx)*fy, w10 = fx*(1.f-fy), w11 = fx*fy;
        float wz0 = 1.f - fz, wz1 = fz;

        float wt[8];
        wt[0]=w00*wz0; wt[1]=w00*wz1; wt[2]=w01*wz0; wt[3]=w01*wz1;
        wt[4]=w10*wz0; wt[5]=w10*wz1; wt[6]=w11*wz0; wt[7]=w11*wz1;
        int off[8];
        off[0]=vb;          off[1]=vb+1;
        off[2]=vb+WORLD;    off[3]=vb+WORLD+1;
        off[4]=vb+S2;       off[5]=vb+S2+1;
        off[6]=vb+S2+WORLD; off[7]=vb+S2+WORLD+1;

        float acc[12];
        #pragma unroll
        for (int c = 0; c < 12; c++) acc[c] = 0.0f;
        float dsum = 0.0f;

        #pragma unroll
        for (int u = 0; u < 8; u++) {
            const uint4* rec = &g_pack[(size_t)off[u]*2];
            uint4 qa = __ldg(&rec[0]);
            uint4 qb = __ldg(&rec[1]);
            float wtu = wt[u];
            float2 f;
            f = __half22float2(*(const __half2*)&qa.x); acc[0] += wtu*f.x; acc[1] += wtu*f.y;
            f = __half22float2(*(const __half2*)&qa.y); acc[2] += wtu*f.x; acc[3] += wtu*f.y;
            f = __half22float2(*(const __half2*)&qa.z); acc[4] += wtu*f.x; acc[5] += wtu*f.y;
            f = __half22float2(*(const __half2*)&qa.w); acc[6] += wtu*f.x; acc[7] += wtu*f.y;
            f = __half22float2(*(const __half2*)&qb.x); acc[8] += wtu*f.x; acc[9] += wtu*f.y;
            f = __half22float2(*(const __half2*)&qb.y); acc[10]+= wtu*f.x; acc[11]+= wtu*f.y;
            dsum += wtu * __uint_as_float(qb.z);
        }

        float x = dsum + ACT_SHIFT;
        float sp = (x > 20.0f) ? x : log1pf(expf(x));
        float alpha = valid ? (1.0f - expf(-interval * sp)) : 0.0f;

        if (valid) {
            uint32_t ph[8];
            #pragma unroll
            for (int c = 0; c < 6; c++) ph[c] = pack_h2(acc[2*c], acc[2*c+1]);
            ph[6] = ph[7] = 0u;
            uint4* dh = (uint4*)&g_f16[(size_t)(base + p)*16];
            dh[0] = make_uint4(ph[0],ph[1],ph[2],ph[3]);
            dh[1] = make_uint4(ph[4],ph[5],ph[6],ph[7]);
        }

        float q = 1.0f - alpha;
        float incl = q;
        #pragma unroll
        for (int dlt = 1; dlt < 32; dlt <<= 1) {
            float o = __shfl_up_sync(0xffffffffu, incl, dlt);
            if (lane >= dlt) incl *= o;
        }
        float excl = __shfl_up_sync(0xffffffffu, incl, 1);
        if (lane == 0) excl = 1.0f;
        if (valid) g_w[base + p] = alpha * T * excl;
        float tot = __shfl_sync(0xffffffffu, incl, 31);
        T *= tot;
    }
    if (lane == 0) {
        out[gw*3+0] = T; out[gw*3+1] = T; out[gw*3+2] = T;   // BG = 1.0
    }
}

// ---------------- K2b: per-ray layer0 view contribution (fp16): h0v = b0 + vemb @ W0[12:39] ----------------
__global__ void k_h0v(const float* __restrict__ w0, const float* __restrict__ b0)
{
    int gid = blockIdx.x * blockDim.x + threadIdx.x;
    int r = gid >> 7, n = gid & 127;
    float acc = __ldg(&b0[n]);
    #pragma unroll
    for (int k = 0; k < 27; k++)
        acc = fmaf(g_vembf[r*27 + k], __ldg(&w0[(12+k)*128 + n]), acc);
    g_h0v[r*128 + n] = f2h(acc);
}

// ---------------- K3: persistent fp16-acc MLP, 256 thr (8 warps, M=16/warp), 3 CTAs/SM ----------------
// smem layout (bytes)
#define SM_B1V   0        // 512:   b1 as half2[64] (256 B used)
#define SM_H0    512      // 1024:  [2 buf][2 rays][128 half]
#define SM_A0    1536     // 12288: [2 buf][128 rows][48 B]
#define SM_B0    13824    // 6144:  [128 n][48 B] (k 0..15 real)
#define SM_B1    19968    // 34816: [128 n][272 B] (k 0..127 real)
#define SM_B2    54784    // 2176:  [8 n][272 B] (n 0..2 real)
#define SMEM_TOTAL 56960

__global__ void __launch_bounds__(256, 3) k_mlp(
    const float* __restrict__ w0, const float* __restrict__ b0,
    const float* __restrict__ w1, const float* __restrict__ b1,
    const float* __restrict__ w2, const float* __restrict__ b2,
    float* __restrict__ out)
{
    extern __shared__ unsigned char smem[];
    uint32_t sb = smem_u32(smem);
    int tid = threadIdx.x;
    int w = tid >> 5, l = tid & 31;
    int g = l >> 2, tg = l & 3;

    // ---- one-time weight staging (fp16, [n][k] layout) ----
    if (tid < 64) ((uint32_t*)(smem + SM_B1V))[tid] = pack_h2(b1[2*tid], b1[2*tid+1]);

    for (int idx = tid; idx < 128*16; idx += 256) {
        int n = idx & 127, k = idx >> 7;
        float v = (k < 12) ? w0[k*128 + n] : 0.0f;
        *(uint16_t*)(smem + SM_B0 + n*48 + k*2) = f2h(v);
    }
    for (int idx = tid; idx < 128*128; idx += 256) {
        int n = idx & 127, k = idx >> 7;
        *(uint16_t*)(smem + SM_B1 + n*272 + k*2) = f2h(w1[k*128 + n]);
    }
    for (int idx = tid; idx < 8*128; idx += 256) {
        int n = idx & 7, k = idx >> 3;
        float v = (n < 3) ? w2[k*3 + n] : 0.0f;
        *(uint16_t*)(smem + SM_B2 + n*272 + k*2) = f2h(v);
    }
    float b2r0 = __ldg(&b2[0]), b2r1 = __ldg(&b2[1]), b2r2 = __ldg(&b2[2]);
    const __half2* b1h2 = (const __half2*)(smem + SM_B1V);
    const __half2 hz = __floats2half2_rn(0.f, 0.f);

    // ---- lane-invariant ldmatrix addresses ----
    uint32_t rowA = 16u*w + (l & 7) + ((l >> 3) & 1) * 8;   // this warp's 16-row strip
    uint32_t colA = (uint32_t)(l >> 4) * 16;
    uint32_t lrow = (l & 7) + ((l >> 4) & 1) * 8;
    uint32_t lcol = ((l >> 3) & 1) * 16;
    uint32_t aB0 = sb + SM_B0 + lrow*48  + lcol;
    uint32_t aB1 = sb + SM_B1 + lrow*272 + lcol;
    uint32_t aB2 = sb + SM_B2 + (uint32_t)(l & 7)*272 + ((l >> 3) & 1)*16;

    // staging: 256 threads, each stages 16B (half a row)
    int strow = tid >> 1, stpart = tid & 1;
    uint32_t a0dst0 = sb + SM_A0 + strow*48 + stpart*16;

    // ---- prime A0 + H0 buffer 0 (cp.async) ----
    int m = blockIdx.x;
    if (m < NTILES) {
        CP_ASYNC16(a0dst0, (const char*)&g_f16[(size_t)(m*128+strow)*16 + stpart*8]);
        int rA = (m*128) / PSTEPS;
        int rB = (m*128 + 127) / PSTEPS;
        if (tid < 128) {
            int ray = (tid < 64) ? rA : rB;
            int li  = tid & 63;
            CP_ASYNC4(sb + SM_H0 + (uint32_t)(tid < 64 ? 0 : 256) + li*4,
                      (const char*)&g_h0v[(size_t)ray*128 + li*2]);
        }
        CP_COMMIT();
        CP_WAIT0();
    }
    __syncthreads();

    int buf = 0;

    for (; m < NTILES; m += gridDim.x) {
        int mbase = m * 128;
        int mn = m + gridDim.x;
        bool hn = mn < NTILES;
        if (hn) {   // async-stage next tile into alternate buffer (hidden under compute)
            CP_ASYNC16(a0dst0 + (uint32_t)(buf^1)*6144u,
                       (const char*)&g_f16[(size_t)(mn*128+strow)*16 + stpart*8]);
            int rAn = (mn*128) / PSTEPS;
            int rBn = (mn*128 + 127) / PSTEPS;
            if (tid < 128) {
                int ray = (tid < 64) ? rAn : rBn;
                int li  = tid & 63;
                CP_ASYNC4(sb + SM_H0 + (uint32_t)(buf^1)*512u + (uint32_t)(tid < 64 ? 0 : 256) + li*4,
                          (const char*)&g_h0v[(size_t)ray*128 + li*2]);
            }
            CP_COMMIT();
        }

        // sample ids for this warp's 16-row strip
        int s0 = mbase + 16*w + g;
        int s1 = s0 + 8;
        int r0 = s0 / PSTEPS, r1 = s1 / PSTEPS;
        int rAc = mbase / PSTEPS;
        const __half* h0sb = (const __half*)(smem + SM_H0 + (uint32_t)buf*512u);
        const __half* hp0 = h0sb + ((r0 != rAc) ? 128 : 0);
        const __half* hp1 = h0sb + ((r1 != rAc) ? 128 : 0);

        // ---- layer 0: K=16, f16-acc MMA -> A1 frags in registers ----
        uint32_t aA = sb + SM_A0 + (uint32_t)buf*6144u + rowA*48 + colA;
        uint32_t a0f[4];
        LDSM_X4(a0f[0],a0f[1],a0f[2],a0f[3], aA);

        uint32_t aF[8][4];
        #pragma unroll
        for (int p = 0; p < 8; p++) {
            uint32_t cc[2][2];
            cc[0][0]=cc[0][1]=cc[1][0]=cc[1][1]=0u;
            uint32_t bb0,bb1,bb2,bb3;
            LDSM_X4(bb0,bb1,bb2,bb3, aB0 + p*768);
            MMA_F16H(cc[0], a0f[0],a0f[1],a0f[2],a0f[3], bb0,bb1);
            MMA_F16H(cc[1], a0f[0],a0f[1],a0f[2],a0f[3], bb2,bb3);
            #pragma unroll
            for (int hh = 0; hh < 2; hh++) {
                int col = p*16 + hh*8 + tg*2;
                __half2 hA = *(const __half2*)&hp0[col];
                __half2 hB = *(const __half2*)&hp1[col];
                __half2 o0 = __hmax2(__hadd2(*(__half2*)&cc[hh][0], hA), hz);
                __half2 o1 = __hmax2(__hadd2(*(__half2*)&cc[hh][1], hB), hz);
                aF[p][0+hh*2] = *(uint32_t*)&o0;
                aF[p][1+hh*2] = *(uint32_t*)&o1;
            }
        }

        // ---- layer 1 (K=128, f16-acc) + fused layer 2 MMA (f32-acc) per 16-col chunk ----
        float c2[4];
        c2[0]=c2[1]=c2[2]=c2[3]=0.f;

        #pragma unroll
        for (int p = 0; p < 8; p++) {
            uint32_t cc[2][2];
            cc[0][0]=cc[0][1]=cc[1][0]=cc[1][1]=0u;
            #pragma unroll
            for (int ks = 0; ks < 8; ks++) {
                uint32_t bb0,bb1,bb2,bb3;
                LDSM_X4(bb0,bb1,bb2,bb3, aB1 + p*4352 + ks*32);
                MMA_F16H(cc[0], aF[ks][0],aF[ks][1],aF[ks][2],aF[ks][3], bb0,bb1);
                MMA_F16H(cc[1], aF[ks][0],aF[ks][1],aF[ks][2],aF[ks][3], bb2,bb3);
            }
            uint32_t hf[4];
            #pragma unroll
            for (int hh = 0; hh < 2; hh++) {
                int col = p*16 + hh*8 + tg*2;
                __half2 bh = b1h2[col >> 1];
                __half2 o0 = __hmax2(__hadd2(*(__half2*)&cc[hh][0], bh), hz);
                __half2 o1 = __hmax2(__hadd2(*(__half2*)&cc[hh][1], bh), hz);
                hf[0+hh*2] = *(uint32_t*)&o0;
                hf[1+hh*2] = *(uint32_t*)&o1;
            }
            uint32_t b2a, b2b;
            LDSM_X2(b2a, b2b, aB2 + p*32);
            MMA_F16(c2, hf[0],hf[1],hf[2],hf[3], b2a, b2b);
        }

        // ---- epilogue: sigmoid + weighted atomic, direct from c2 fragments ----
        if (tg == 0) {
            float wgA = g_w[s0], wgB = g_w[s1];
            atomicAdd(&out[r0*3+0], wgA / (1.0f + __expf(-(c2[0] + b2r0))));
            atomicAdd(&out[r0*3+1], wgA / (1.0f + __expf(-(c2[1] + b2r1))));
            atomicAdd(&out[r1*3+0], wgB / (1.0f + __expf(-(c2[2] + b2r0))));
            atomicAdd(&out[r1*3+1], wgB / (1.0f + __expf(-(c2[3] + b2r1))));
        } else if (tg == 1) {
            float wgA = g_w[s0], wgB = g_w[s1];
            atomicAdd(&out[r0*3+2], wgA / (1.0f + __expf(-(c2[0] + b2r2))));
            atomicAdd(&out[r1*3+2], wgB / (1.0f + __expf(-(c2[2] + b2r2))));
        }

        if (hn) CP_WAIT0();
        __syncthreads();
        buf ^= 1;
    }
}

// ---------------- launcher ----------------
extern "C" void kernel_launch(void* const* d_in, const int* in_sizes, int n_in,
                              void* d_out, int out_size)
{
    const float* rays_o   = (const float*)d_in[0];
    const float* rays_d   = (const float*)d_in[1];
    const float* viewdirs = (const float*)d_in[2];
    const float* dgrid    = (const float*)d_in[3];
    const float* k0g      = (const float*)d_in[4];
    const float* w0 = (const float*)d_in[5];
    const float* b0 = (const float*)d_in[6];
    const float* w1 = (const float*)d_in[7];
    const float* b1 = (const float*)d_in[8];
    const float* w2 = (const float*)d_in[9];
    const float* b2 = (const float*)d_in[10];
    const int* stepsize = (const int*)d_in[11];
    float* out = (float*)d_out;

    cudaFuncSetAttribute(k_mlp, cudaFuncAttributeMaxDynamicSharedMemorySize, SMEM_TOTAL);

    k_pack<<<(S3 + 255) / 256, 256>>>(dgrid, k0g);
    k_sample<<<(N_RAYS * 32 + 255) / 256, 256>>>(rays_o, rays_d, viewdirs, stepsize, out);
    k_h0v<<<(N_RAYS * 128) / 256, 256>>>(w0, b0);
    k_mlp<<<GRID_MLP, 256, SMEM_TOTAL>>>(w0, b0, w1, b1, w2, b2, out);
}